// round 4
// baseline (speedup 1.0000x reference)
#include <cuda_runtime.h>
#include <cuda_bf16.h>
#include <math.h>
#include <stdint.h>

// Problem constants
#define Bq 2
#define Tq 2048
#define Cq 1024
#define Hq 16
#define HDq 64
#define Mq (Bq*Tq)          // 4096

// ---------------------------------------------------------------------------
// Device-global scratch (no allocation allowed)
// ---------------------------------------------------------------------------
__device__ float g_Q[(size_t)Bq*Hq*Tq*HDq];   // [B,H,T,HD]
__device__ float g_K[(size_t)Bq*Hq*Tq*HDq];
__device__ float g_V[(size_t)Bq*Hq*Tq*HDq];
__device__ float g_O[(size_t)Bq*Tq*Cq];       // merged heads [B,T,C]
__device__ __nv_bfloat16 g_Ahi[(size_t)Mq*Cq];  // split activations [M,K]
__device__ __nv_bfloat16 g_Alo[(size_t)Mq*Cq];
__device__ __nv_bfloat16 g_Whi[(size_t)Cq*Cq];  // split+TRANSPOSED weights [N,K]
__device__ __nv_bfloat16 g_Wlo[(size_t)Cq*Cq];

// ---------------------------------------------------------------------------
// PTX helpers (arch-agnostic: sm_80+ instructions only)
// ---------------------------------------------------------------------------
__device__ __forceinline__ uint32_t smem_u32(const void* p){
    uint32_t a;
    asm("{ .reg .u64 t; cvta.to.shared.u64 t, %1; cvt.u32.u64 %0, t; }"
        : "=r"(a) : "l"(p));
    return a;
}
__device__ __forceinline__ void cpa16(uint32_t s, const void* g){
    asm volatile("cp.async.cg.shared.global [%0], [%1], 16;" :: "r"(s), "l"(g));
}
__device__ __forceinline__ void cp_commit(){
    asm volatile("cp.async.commit_group;" ::: "memory");
}
__device__ __forceinline__ void cp_wait_all(){
    asm volatile("cp.async.wait_group 0;" ::: "memory");
}
__device__ __forceinline__ void ldsm4(uint32_t* r, uint32_t addr){
    asm volatile("ldmatrix.sync.aligned.m8n8.x4.shared.b16 {%0,%1,%2,%3}, [%4];"
                 : "=r"(r[0]), "=r"(r[1]), "=r"(r[2]), "=r"(r[3]) : "r"(addr));
}
__device__ __forceinline__ void mma16816(float* c, const uint32_t* a, const uint32_t* b){
    asm volatile(
        "mma.sync.aligned.m16n8k16.row.col.f32.bf16.bf16.f32 "
        "{%0,%1,%2,%3}, {%4,%5,%6,%7}, {%8,%9}, {%0,%1,%2,%3};"
        : "+f"(c[0]), "+f"(c[1]), "+f"(c[2]), "+f"(c[3])
        : "r"(a[0]), "r"(a[1]), "r"(a[2]), "r"(a[3]), "r"(b[0]), "r"(b[1]));
}
__device__ __forceinline__ uint32_t sw128(uint32_t o){ return o ^ ((o >> 3) & 0x70); }

// ---------------------------------------------------------------------------
// Split kernels: fp32 -> bf16 hi + bf16 lo (residual)
// ---------------------------------------------------------------------------
__global__ __launch_bounds__(256)
void split_ew(const float4* __restrict__ X, __nv_bfloat162* __restrict__ hi,
              __nv_bfloat162* __restrict__ lo)
{
    int i = blockIdx.x * 256 + threadIdx.x;   // over Mq*Cq/4 float4s
    float4 x = X[i];
    __nv_bfloat16 h0 = __float2bfloat16(x.x);
    __nv_bfloat16 h1 = __float2bfloat16(x.y);
    __nv_bfloat16 h2 = __float2bfloat16(x.z);
    __nv_bfloat16 h3 = __float2bfloat16(x.w);
    hi[2*i+0] = __nv_bfloat162(h0, h1);
    hi[2*i+1] = __nv_bfloat162(h2, h3);
    lo[2*i+0] = __nv_bfloat162(__float2bfloat16(x.x - __bfloat162float(h0)),
                               __float2bfloat16(x.y - __bfloat162float(h1)));
    lo[2*i+1] = __nv_bfloat162(__float2bfloat16(x.z - __bfloat162float(h2)),
                               __float2bfloat16(x.w - __bfloat162float(h3)));
}

// W is [K,N] row-major; emit transposed split [N,K]
__global__ __launch_bounds__(256)
void split_wT(const float* __restrict__ W, __nv_bfloat16* __restrict__ hiT,
              __nv_bfloat16* __restrict__ loT)
{
    __shared__ float tl[32][33];
    int tx = threadIdx.x, ty = threadIdx.y;       // 32 x 8
    int n0 = blockIdx.x * 32, k0 = blockIdx.y * 32;
    #pragma unroll
    for (int i = 0; i < 4; i++)
        tl[ty + 8*i][tx] = W[(size_t)(k0 + ty + 8*i) * Cq + n0 + tx];
    __syncthreads();
    #pragma unroll
    for (int i = 0; i < 4; i++) {
        float v = tl[tx][ty + 8*i];               // = W[k0+tx, n0+ty+8i]
        __nv_bfloat16 h = __float2bfloat16(v);
        size_t o = (size_t)(n0 + ty + 8*i) * Cq + k0 + tx;
        hiT[o] = h;
        loT[o] = __float2bfloat16(v - __bfloat162float(h));
    }
}

// ---------------------------------------------------------------------------
// mma.sync GEMM: out[M,N] = A[M,K] * Wt[N,K]^T + bias, 3-product bf16 split.
// Tile 128x128, BK=64, 8 warps (2M x 4N -> 64x32 warp tiles),
// double-buffered cp.async, SW128 swizzle + ldmatrix.
// ---------------------------------------------------------------------------
#define KT 64
#define NCHUNK (Cq/KT)            // 16
#define OPB 16384                 // one 128x64 bf16 operand tile
#define STAGEB (4*OPB)            // Ahi,Alo,Bhi,Blo = 64KB
#define GEMM_SMEM (2*STAGEB)      // 128KB

template<bool HEADOUT>
__global__ __launch_bounds__(256)
void gemm_mma(const __nv_bfloat16* __restrict__ Ahi, const __nv_bfloat16* __restrict__ Alo,
              const __nv_bfloat16* __restrict__ Bhi, const __nv_bfloat16* __restrict__ Blo,
              const float* __restrict__ bias, float* __restrict__ out)
{
    extern __shared__ char smem[];
    const uint32_t sb  = smem_u32(smem);
    const int tid = threadIdx.x, wid = tid >> 5, lane = tid & 31;
    const int bm = blockIdx.y * 128, bn = blockIdx.x * 128;
    const int wm = wid & 1;        // 0..1 -> rows wm*64
    const int wn = wid >> 1;       // 0..3 -> cols wn*32

    const __nv_bfloat16* gAh = Ahi + (size_t)bm * Cq;
    const __nv_bfloat16* gAl = Alo + (size_t)bm * Cq;
    const __nv_bfloat16* gBh = Bhi + (size_t)bn * Cq;
    const __nv_bfloat16* gBl = Blo + (size_t)bn * Cq;

    auto load_chunk = [&](int c) {
        uint32_t stb = sb + (uint32_t)(c & 1) * STAGEB;
        int koff = c * KT;
        #pragma unroll
        for (int t = 0; t < 4; t++) {
            int idx  = tid + t * 256;          // 0..1023
            int row  = idx >> 3;               // 0..127
            int c16  = idx & 7;                // 16B chunk within 128B row
            uint32_t so = sw128((uint32_t)(row * 128 + c16 * 16));
            size_t   go = (size_t)row * Cq + koff + c16 * 8;
            cpa16(stb + 0*OPB + so, gAh + go);
            cpa16(stb + 1*OPB + so, gAl + go);
            cpa16(stb + 2*OPB + so, gBh + go);
            cpa16(stb + 3*OPB + so, gBl + go);
        }
    };

    float acc[4][4][4];
    #pragma unroll
    for (int i = 0; i < 4; i++)
        #pragma unroll
        for (int j = 0; j < 4; j++)
            #pragma unroll
            for (int r = 0; r < 4; r++) acc[i][j][r] = 0.f;

    // ldmatrix lane-address bases (byte offsets within an operand tile)
    // A x4: lanes 0-15 -> rows 0-15 @ k0 ; lanes 16-31 -> rows 0-15 @ k0+8
    const uint32_t aOff = (uint32_t)(wm*64 + (lane & 15)) * 128 + (uint32_t)((lane >> 4) * 8) * 2;
    // B x4 over [n,k] tile: lane/8 groups -> {n0-7@k0, n0-7@k8, n8-15@k0, n8-15@k8}
    const uint32_t bOff = (uint32_t)(wn*32 + (lane & 7) + ((lane >> 4) & 1) * 8) * 128
                        + (uint32_t)(((lane >> 3) & 1) * 8) * 2;

    load_chunk(0);
    cp_commit();

    for (int c = 0; c < NCHUNK; c++) {
        cp_wait_all();
        __syncthreads();
        if (c + 1 < NCHUNK) { load_chunk(c + 1); cp_commit(); }

        uint32_t stb = sb + (uint32_t)(c & 1) * STAGEB;
        #pragma unroll
        for (int ks = 0; ks < 4; ks++) {
            uint32_t k2 = (uint32_t)ks * 32;   // k0*2 bytes
            uint32_t Ah[4][4], Al[4][4], Bh[4][2], Bl[4][2];
            #pragma unroll
            for (int i = 0; i < 4; i++) {
                uint32_t o = sw128(aOff + (uint32_t)i * 2048 + k2);
                ldsm4(Ah[i], stb + 0*OPB + o);
                ldsm4(Al[i], stb + 1*OPB + o);
            }
            #pragma unroll
            for (int jp = 0; jp < 2; jp++) {
                uint32_t o = sw128(bOff + (uint32_t)jp * 2048 + k2);
                uint32_t r[4];
                ldsm4(r, stb + 2*OPB + o);
                Bh[jp*2][0] = r[0]; Bh[jp*2][1] = r[1];
                Bh[jp*2+1][0] = r[2]; Bh[jp*2+1][1] = r[3];
                ldsm4(r, stb + 3*OPB + o);
                Bl[jp*2][0] = r[0]; Bl[jp*2][1] = r[1];
                Bl[jp*2+1][0] = r[2]; Bl[jp*2+1][1] = r[3];
            }
            #pragma unroll
            for (int i = 0; i < 4; i++)
                #pragma unroll
                for (int j = 0; j < 4; j++) {
                    mma16816(acc[i][j], Ah[i], Bh[j]);
                    mma16816(acc[i][j], Ah[i], Bl[j]);
                    mma16816(acc[i][j], Al[i], Bh[j]);
                }
        }
    }

    // Epilogue: bias + direct (float2) stores
    #pragma unroll
    for (int j = 0; j < 4; j++) {
        int n = bn + wn*32 + j*8 + (lane & 3) * 2;
        float b0 = __ldg(&bias[n]), b1 = __ldg(&bias[n + 1]);
        #pragma unroll
        for (int i = 0; i < 4; i++) {
            int m0 = bm + wm*64 + i*16 + (lane >> 2);
            #pragma unroll
            for (int h2 = 0; h2 < 2; h2++) {
                int m = m0 + h2*8;
                float v0 = acc[i][j][h2*2+0] + b0;
                float v1 = acc[i][j][h2*2+1] + b1;
                size_t o;
                if (HEADOUT) {
                    int b = m >> 11, tt = m & (Tq - 1);
                    int h = n >> 6,  dd = n & 63;
                    o = (((size_t)(b*Hq + h) * Tq) + tt) * HDq + dd;
                } else {
                    o = (size_t)m * Cq + n;
                }
                *reinterpret_cast<float2*>(&out[o]) = make_float2(v0, v1);
            }
        }
    }
}

// ---------------------------------------------------------------------------
// Flash attention, fp32 (unchanged)
// ---------------------------------------------------------------------------
__global__ __launch_bounds__(64)
void attn_kernel(const float* __restrict__ Q, const float* __restrict__ K,
                 const float* __restrict__ V, float* __restrict__ O)
{
    __shared__ float Ks[64*64];
    __shared__ float Vs[64*64];
    __shared__ float Ss[64*65];

    const int tid = threadIdx.x;
    const int qt  = blockIdx.x * 64;
    const int h   = blockIdx.y;
    const int b   = blockIdx.z;

    const size_t headbase = ((size_t)(b*Hq + h) * Tq) * HDq;
    const float* Qb = Q + headbase;
    const float* Kb = K + headbase;
    const float* Vb = V + headbase;

    float q[64], o[64];
    {
        const float4* q4 = reinterpret_cast<const float4*>(Qb + (size_t)(qt + tid) * HDq);
        #pragma unroll
        for (int c = 0; c < 16; c++) {
            float4 v = q4[c];
            q[c*4+0] = v.x; q[c*4+1] = v.y; q[c*4+2] = v.z; q[c*4+3] = v.w;
        }
        #pragma unroll
        for (int c = 0; c < 64; c++) o[c] = 0.f;
    }

    float m = -INFINITY, l = 0.f;
    const float scale = 0.125f;

    for (int kt = 0; kt < Tq; kt += 64) {
        {
            const float4* Kg4 = reinterpret_cast<const float4*>(Kb + (size_t)kt * HDq);
            const float4* Vg4 = reinterpret_cast<const float4*>(Vb + (size_t)kt * HDq);
            float4* Ks4 = reinterpret_cast<float4*>(Ks);
            float4* Vs4 = reinterpret_cast<float4*>(Vs);
            #pragma unroll
            for (int s = 0; s < 16; s++) {
                Ks4[tid + s*64] = Kg4[tid + s*64];
                Vs4[tid + s*64] = Vg4[tid + s*64];
            }
        }
        __syncthreads();

        float tmax = -INFINITY;
        #pragma unroll 4
        for (int j = 0; j < 64; j++) {
            float s = 0.f;
            #pragma unroll
            for (int c = 0; c < 64; c++) s += q[c] * Ks[j*64 + c];
            s *= scale;
            Ss[tid*65 + j] = s;
            tmax = fmaxf(tmax, s);
        }

        float mnew  = fmaxf(m, tmax);
        float alpha = __expf(m - mnew);
        l *= alpha;
        #pragma unroll
        for (int c = 0; c < 64; c++) o[c] *= alpha;
        m = mnew;

        #pragma unroll 2
        for (int j = 0; j < 64; j++) {
            float p = __expf(Ss[tid*65 + j] - mnew);
            l += p;
            #pragma unroll
            for (int c = 0; c < 64; c++) o[c] += p * Vs[j*64 + c];
        }
        __syncthreads();
    }

    const float inv = 1.f / l;
    float4* Ob = reinterpret_cast<float4*>(
        O + ((size_t)(b*Tq) + qt + tid) * Cq + h * HDq);
    #pragma unroll
    for (int c = 0; c < 16; c++) {
        float4 v;
        v.x = o[c*4+0]*inv; v.y = o[c*4+1]*inv;
        v.z = o[c*4+2]*inv; v.w = o[c*4+3]*inv;
        Ob[c] = v;
    }
}

// ---------------------------------------------------------------------------
// Launch
// ---------------------------------------------------------------------------
extern "C" void kernel_launch(void* const* d_in, const int* in_sizes, int n_in,
                              void* d_out, int out_size)
{
    (void)in_sizes; (void)n_in; (void)out_size;
    const float* queries = (const float*)d_in[0];
    const float* keys    = (const float*)d_in[1];
    const float* values  = (const float*)d_in[2];
    const float* Wq = (const float*)d_in[3];
    const float* bq = (const float*)d_in[4];
    const float* Wk = (const float*)d_in[5];
    const float* bk = (const float*)d_in[6];
    const float* Wv = (const float*)d_in[7];
    const float* bv = (const float*)d_in[8];
    const float* Wo = (const float*)d_in[9];
    const float* bo = (const float*)d_in[10];
    float* out = (float*)d_out;

    float *pQ, *pK, *pV, *pO;
    __nv_bfloat16 *pAh, *pAl, *pWh, *pWl;
    cudaGetSymbolAddress((void**)&pQ,  g_Q);
    cudaGetSymbolAddress((void**)&pK,  g_K);
    cudaGetSymbolAddress((void**)&pV,  g_V);
    cudaGetSymbolAddress((void**)&pO,  g_O);
    cudaGetSymbolAddress((void**)&pAh, g_Ahi);
    cudaGetSymbolAddress((void**)&pAl, g_Alo);
    cudaGetSymbolAddress((void**)&pWh, g_Whi);
    cudaGetSymbolAddress((void**)&pWl, g_Wlo);

    cudaFuncSetAttribute(gemm_mma<true>,  cudaFuncAttributeMaxDynamicSharedMemorySize, GEMM_SMEM);
    cudaFuncSetAttribute(gemm_mma<false>, cudaFuncAttributeMaxDynamicSharedMemorySize, GEMM_SMEM);

    dim3 gsplit(Mq*Cq/4/256);              // 4096
    dim3 gwT(Cq/32, Cq/32), bwT(32, 8);    // (32,32)
    dim3 gg(Cq/128, Mq/128);               // (8, 32)

    // Q projection
    split_ew<<<gsplit, 256>>>((const float4*)queries, (__nv_bfloat162*)pAh, (__nv_bfloat162*)pAl);
    split_wT<<<gwT, bwT>>>(Wq, pWh, pWl);
    gemm_mma<true><<<gg, 256, GEMM_SMEM>>>(pAh, pAl, pWh, pWl, bq, pQ);
    // K projection
    split_ew<<<gsplit, 256>>>((const float4*)keys, (__nv_bfloat162*)pAh, (__nv_bfloat162*)pAl);
    split_wT<<<gwT, bwT>>>(Wk, pWh, pWl);
    gemm_mma<true><<<gg, 256, GEMM_SMEM>>>(pAh, pAl, pWh, pWl, bk, pK);
    // V projection
    split_ew<<<gsplit, 256>>>((const float4*)values, (__nv_bfloat162*)pAh, (__nv_bfloat162*)pAl);
    split_wT<<<gwT, bwT>>>(Wv, pWh, pWl);
    gemm_mma<true><<<gg, 256, GEMM_SMEM>>>(pAh, pAl, pWh, pWl, bv, pV);

    // attention
    dim3 ga(Tq/64, Hq, Bq);
    attn_kernel<<<ga, 64>>>(pQ, pK, pV, pO);

    // output projection
    split_ew<<<gsplit, 256>>>((const float4*)pO, (__nv_bfloat162*)pAh, (__nv_bfloat162*)pAl);
    split_wT<<<gwT, bwT>>>(Wo, pWh, pWl);
    gemm_mma<false><<<gg, 256, GEMM_SMEM>>>(pAh, pAl, pWh, pWl, bo, out);
}